// round 4
// baseline (speedup 1.0000x reference)
#include <cuda_runtime.h>
#include <cuda_fp16.h>
#include <cstdint>

// ---------------------------------------------------------------------------
// Problem constants
// ---------------------------------------------------------------------------
#define M_DIM 4096
#define N_DIM 11008
#define K_DIM 4096
#define GROUP 128

#define BM 128            // CTA M tile
#define BN 256            // CTA N tile
#define KC 64             // K halves per pipeline chunk (= 128 bytes per row)
#define NKC (K_DIM / KC)  // 64 chunks
#define NMT (M_DIM / BM)  // 32
#define NNT (N_DIM / BN)  // 43

#define A_BLK_BYTES (BM * 128)       // 16384
#define B_BLK_BYTES (BN * 128)       // 32768
#define STAGE_BYTES (A_BLK_BYTES + B_BLK_BYTES)  // 49152
#define NSTAGES 4
#define SM_TOTAL (2048 + NSTAGES * STAGE_BYTES)  // 198656

// Tiled+swizzled scratch in GMEM
__device__ uint4 g_A[(size_t)NMT * NKC * A_BLK_BYTES / 16];   // 33.5 MB
__device__ uint4 g_B[(size_t)NNT * NKC * B_BLK_BYTES / 16];   // 90.2 MB

__host__ __device__ __forceinline__ uint32_t swz128(uint32_t off) {
    return off ^ ((off >> 3) & 0x70u);
}

// ---------------------------------------------------------------------------
// PTX helpers (sm_90-level only; tcgen05 is NOT available in this build path)
// ---------------------------------------------------------------------------
__device__ __forceinline__ uint32_t smem_u32(const void* p) {
    uint32_t a;
    asm("{ .reg .u64 t; cvta.to.shared.u64 t, %1; cvt.u32.u64 %0, t; }" : "=r"(a) : "l"(p));
    return a;
}

#define MBAR_INIT(addr, cnt) \
    asm volatile("mbarrier.init.shared.b64 [%0], %1;" :: "r"(addr), "r"(cnt) : "memory")

#define MBAR_EXPECT_TX(addr, bytes) \
    asm volatile("mbarrier.arrive.expect_tx.shared.b64 _, [%0], %1;" :: "r"(addr), "r"(bytes) : "memory")

#define MBAR_ARRIVE(addr) \
    asm volatile("mbarrier.arrive.shared.b64 _, [%0];" :: "r"(addr) : "memory")

#define MBAR_WAIT(addr, parity) do {                                        \
    uint32_t _m = (addr); uint32_t _p = (parity); uint32_t _d;              \
    asm volatile("{\n\t.reg .pred p;\n\t"                                   \
        "mbarrier.try_wait.parity.acquire.cta.shared::cta.b64 p, [%1], %2;\n\t" \
        "selp.b32 %0, 1, 0, p;\n\t}"                                        \
        : "=r"(_d) : "r"(_m), "r"(_p) : "memory");                          \
    if (!_d) {                                                              \
        asm volatile("{\n\t.reg .pred P1;\n\t"                              \
            "W0_%=:\n\t"                                                    \
            "mbarrier.try_wait.parity.acquire.cta.shared::cta.b64 P1, [%0], %1, 0x989680;\n\t" \
            "@P1 bra.uni W1_%=;\n\t"                                        \
            "bra.uni W0_%=;\n\t"                                            \
            "W1_%=:\n\t}" :: "r"(_m), "r"(_p) : "memory");                  \
    }                                                                       \
} while (0)

__device__ __forceinline__ void bulk_ld(uint32_t dst, const void* src, uint32_t bytes,
                                        uint32_t mbar) {
    asm volatile(
        "cp.async.bulk.shared::cluster.global.mbarrier::complete_tx::bytes [%0], [%1], %2, [%3];"
        :: "r"(dst), "l"(src), "r"(bytes), "r"(mbar) : "memory");
}

__device__ __forceinline__ void ldsm4(uint32_t* r, uint32_t addr) {
    asm volatile("ldmatrix.sync.aligned.m8n8.x4.shared.b16 {%0,%1,%2,%3}, [%4];\n"
                 : "=r"(r[0]), "=r"(r[1]), "=r"(r[2]), "=r"(r[3]) : "r"(addr));
}
__device__ __forceinline__ void mma16816(float* c, const uint32_t* a, uint32_t b0, uint32_t b1) {
    asm volatile(
        "mma.sync.aligned.m16n8k16.row.col.f32.f16.f16.f32 "
        "{%0,%1,%2,%3}, {%4,%5,%6,%7}, {%8,%9}, {%0,%1,%2,%3};\n"
        : "+f"(c[0]), "+f"(c[1]), "+f"(c[2]), "+f"(c[3])
        : "r"(a[0]), "r"(a[1]), "r"(a[2]), "r"(a[3]), "r"(b0), "r"(b1));
}

// ---------------------------------------------------------------------------
// Kernel 1 (merged prep):
//   blocks [0, 16384):     x' = H (s2 * H (s1 * x)) / 128 -> tiled swizzled A
//   blocks [16384, 104448): dequant W -> tiled swizzled B
// ---------------------------------------------------------------------------
#define PREP_X_BLOCKS (M_DIM * 32 / 8)                 // 16384
#define PREP_W_BLOCKS (N_DIM * (K_DIM / 2) / 256)      // 88064

__global__ __launch_bounds__(256) void prep_kernel(
    const float* __restrict__ x, const float* __restrict__ s1,
    const float* __restrict__ s2, unsigned char* __restrict__ At,
    const int* __restrict__ pw, const float* __restrict__ norms,
    const float* __restrict__ cent, unsigned char* __restrict__ Bt) {
    if (blockIdx.x < PREP_X_BLOCKS) {
        // ---------------- transform x (warp-shuffle FWHT) ----------------
        const int lane = threadIdx.x & 31;
        const int wrp = threadIdx.x >> 5;
        const int pair = blockIdx.x * 8 + wrp;
        const int row = pair >> 5;
        const int grp = pair & 31;

        const float4 xv = *(const float4*)(x + (size_t)row * K_DIM + grp * GROUP + lane * 4);
        const float4 s1v = *(const float4*)(s1 + lane * 4);
        const float4 s2v = *(const float4*)(s2 + lane * 4);

        float v[4] = { xv.x * s1v.x, xv.y * s1v.y, xv.z * s1v.z, xv.w * s1v.w };

#pragma unroll
        for (int pass = 0; pass < 2; pass++) {
            float t0 = v[0] + v[1], t1 = v[0] - v[1];
            float t2 = v[2] + v[3], t3 = v[2] - v[3];
            v[0] = t0 + t2; v[2] = t0 - t2;
            v[1] = t1 + t3; v[3] = t1 - t3;
#pragma unroll
            for (int xm = 1; xm <= 16; xm <<= 1) {
                bool hi = (lane & xm) != 0;
#pragma unroll
                for (int j = 0; j < 4; j++) {
                    float o = __shfl_xor_sync(0xFFFFFFFFu, v[j], xm);
                    v[j] = hi ? (o - v[j]) : (v[j] + o);
                }
            }
            if (pass == 0) {
                v[0] *= s2v.x; v[1] *= s2v.y; v[2] *= s2v.z; v[3] *= s2v.w;
            }
        }

        const float sc = 1.0f / 128.0f;
        __half2 h01 = __floats2half2_rn(v[0] * sc, v[1] * sc);
        __half2 h23 = __floats2half2_rn(v[2] * sc, v[3] * sc);

        const int mt = row >> 7, r = row & 127;
        const int e = 4 * lane;
        const int kc = grp * 2 + (e >> 6);
        const int c = e & 63;
        const size_t base = ((size_t)mt * NKC + kc) * A_BLK_BYTES;
        const uint32_t off = swz128((uint32_t)(r * 128 + c * 2));
        uint2 val = { *(uint32_t*)&h01, *(uint32_t*)&h23 };
        *(uint2*)(At + base + off) = val;
    } else {
        // ---------------- dequant W ----------------
        __shared__ float c[16];
        if (threadIdx.x < 16) c[threadIdx.x] = cent[threadIdx.x];
        __syncthreads();

        const int idx = (blockIdx.x - PREP_X_BLOCKS) * 256 + threadIdx.x;
        const int o = idx >> 11;
        const int p = idx & 2047;
        const unsigned b = ((unsigned)pw[idx]) & 0xFFu;
        const float norm = __ldg(&norms[o * 32 + (p >> 6)]);
        __half2 h2 = __floats2half2_rn(c[b & 15u] * norm, c[b >> 4] * norm);

        const int nt = o >> 8, r = o & 255;
        const int kc = p >> 5;
        const uint32_t off = swz128((uint32_t)(r * 128 + (p & 31) * 4));
        const size_t base = ((size_t)nt * NKC + kc) * B_BLK_BYTES;
        *(uint32_t*)(Bt + base + off) = *(uint32_t*)&h2;
    }
}

// ---------------------------------------------------------------------------
// Kernel 2: mma.sync GEMM, 128x256 CTA tile, 8 compute warps (64x64 each)
// + 1 producer warp; 4-stage cp.async.bulk pipeline; fragment double buffer.
// grid = (NMT, NNT): consecutive CTAs share the B tile (L2/DRAM reuse).
// ---------------------------------------------------------------------------
extern __shared__ unsigned char dsm[];

__global__ __launch_bounds__(288, 1) void gemm_kernel(
    const unsigned char* __restrict__ At, const unsigned char* __restrict__ Bt,
    const float* __restrict__ bias, float* __restrict__ C) {
    const int tid = threadIdx.x;
    const int wid = tid >> 5;
    const int lane = tid & 31;
    const uint32_t sb = (smem_u32(dsm) + 1023) & ~1023u;

    const int mt = blockIdx.x;   // fastest: share B across consecutive CTAs
    const int nt = blockIdx.y;
    const unsigned char* Ag = At + (size_t)mt * NKC * A_BLK_BYTES;
    const unsigned char* Bg = Bt + (size_t)nt * NKC * B_BLK_BYTES;

    if (tid == 0) {
#pragma unroll
        for (int s = 0; s < NSTAGES; s++) {
            MBAR_INIT(sb + 8 * s, 1);
            MBAR_INIT(sb + 32 + 8 * s, 8);
        }
        asm volatile("fence.proxy.async.shared::cta;" ::: "memory");
    }
    __syncthreads();

    if (wid == 8) {
        // ---------------- producer warp (lane 0 only) ----------------
        if (lane == 0) {
            for (int j = 0; j < NKC; j++) {
                const int s = j & 3;
                if (j >= NSTAGES) {
                    MBAR_WAIT(sb + 32 + 8 * s, ((j >> 2) - 1) & 1);
                }
                const uint32_t full = sb + 8 * s;
                MBAR_EXPECT_TX(full, STAGE_BYTES);
                const uint32_t st = sb + 1024 + s * STAGE_BYTES;
                bulk_ld(st, Ag + (size_t)j * A_BLK_BYTES, A_BLK_BYTES, full);
                bulk_ld(st + A_BLK_BYTES, Bg + (size_t)j * B_BLK_BYTES, B_BLK_BYTES, full);
            }
        }
        return;
    }

    // ---------------- compute warps 0..7: warp tile 64x64 ----------------
    const int wm = (wid >> 2) * 64;
    const int wn = (wid & 3) * 64;

    float acc[4][8][4];
#pragma unroll
    for (int i = 0; i < 4; i++)
#pragma unroll
        for (int j = 0; j < 8; j++)
#pragma unroll
            for (int k = 0; k < 4; k++) acc[i][j][k] = 0.0f;

    // ldmatrix lane addressing
    const int a_row = lane & 15;
    const int a_colh = (lane >> 4) * 8;
    const int b_row = (lane & 7) + (lane >> 4) * 8;
    const int b_colh = ((lane >> 3) & 1) * 8;

    // double-buffered fragments
    uint32_t afr[2][4][4];
    uint32_t bfr[2][4][4];

    int parity = 0;
    for (int jb = 0; jb < NKC; jb += 4) {
#pragma unroll
        for (int s = 0; s < 4; s++) {
            MBAR_WAIT(sb + 8 * s, parity);
            const uint32_t as = sb + 1024 + s * STAGE_BYTES;
            const uint32_t bs = as + A_BLK_BYTES;

            // preload ks=0 into buffer 0
#pragma unroll
            for (int m = 0; m < 4; m++)
                ldsm4(afr[0][m], as + swz128((uint32_t)((wm + m * 16 + a_row) * 128 + a_colh * 2)));
#pragma unroll
            for (int nb = 0; nb < 4; nb++)
                ldsm4(bfr[0][nb], bs + swz128((uint32_t)((wn + nb * 16 + b_row) * 128 + b_colh * 2)));

#pragma unroll
            for (int ks = 0; ks < 4; ks++) {
                const int cur = ks & 1;
                const int nxt = cur ^ 1;
                if (ks < 3) {
                    const int kq = (ks + 1) * 16;
#pragma unroll
                    for (int m = 0; m < 4; m++)
                        ldsm4(afr[nxt][m],
                              as + swz128((uint32_t)((wm + m * 16 + a_row) * 128 + (kq + a_colh) * 2)));
#pragma unroll
                    for (int nb = 0; nb < 4; nb++)
                        ldsm4(bfr[nxt][nb],
                              bs + swz128((uint32_t)((wn + nb * 16 + b_row) * 128 + (kq + b_colh) * 2)));
                }
#pragma unroll
                for (int m = 0; m < 4; m++) {
#pragma unroll
                    for (int n = 0; n < 8; n++) {
                        mma16816(acc[m][n], afr[cur][m], bfr[cur][n >> 1][(n & 1) * 2],
                                 bfr[cur][n >> 1][(n & 1) * 2 + 1]);
                    }
                }
            }
            if (lane == 0) MBAR_ARRIVE(sb + 32 + 8 * s);
        }
        parity ^= 1;
    }

    // ---------------- epilogue ----------------
    const int gid = lane >> 2;
    const int tq = lane & 3;
    const int bm = mt * BM, bn = nt * BN;
#pragma unroll
    for (int m = 0; m < 4; m++) {
        const int row0 = bm + wm + m * 16 + gid;
#pragma unroll
        for (int n = 0; n < 8; n++) {
            const int col0 = bn + wn + n * 8 + tq * 2;
            const float bz0 = __ldg(&bias[col0]);
            const float bz1 = __ldg(&bias[col0 + 1]);
            float2 v0 = { acc[m][n][0] + bz0, acc[m][n][1] + bz1 };
            float2 v1 = { acc[m][n][2] + bz0, acc[m][n][3] + bz1 };
            *(float2*)(C + (size_t)row0 * N_DIM + col0) = v0;
            *(float2*)(C + (size_t)(row0 + 8) * N_DIM + col0) = v1;
        }
    }
}

// ---------------------------------------------------------------------------
// Launch
// ---------------------------------------------------------------------------
extern "C" void kernel_launch(void* const* d_in, const int* in_sizes, int n_in,
                              void* d_out, int out_size) {
    const float* x     = (const float*)d_in[0];
    const int*   pw    = (const int*)d_in[1];
    const float* norms = (const float*)d_in[2];
    const float* cent  = (const float*)d_in[3];
    const float* s1    = (const float*)d_in[4];
    const float* s2    = (const float*)d_in[5];
    const float* bias  = (const float*)d_in[6];
    float* out = (float*)d_out;

    unsigned char *At, *Bt;
    cudaGetSymbolAddress((void**)&At, g_A);
    cudaGetSymbolAddress((void**)&Bt, g_B);

    prep_kernel<<<PREP_X_BLOCKS + PREP_W_BLOCKS, 256>>>(x, s1, s2, At, pw, norms, cent, Bt);

    static bool attr_set = false;
    if (!attr_set) {
        cudaFuncSetAttribute(gemm_kernel, cudaFuncAttributeMaxDynamicSharedMemorySize,
                             SM_TOTAL);
        attr_set = true;
    }
    dim3 grid(NMT, NNT);
    gemm_kernel<<<grid, 288, SM_TOTAL>>>(At, Bt, bias, out);
}

// round 5
// speedup vs baseline: 1.0304x; 1.0304x over previous
#include <cuda_runtime.h>
#include <cuda_fp16.h>
#include <cstdint>

// ---------------------------------------------------------------------------
// Problem constants
// ---------------------------------------------------------------------------
#define M_DIM 4096
#define N_DIM 11008
#define K_DIM 4096
#define GROUP 128

#define BM 128            // CTA M tile
#define BN 256            // CTA N tile
#define KC 64             // K halves per pipeline chunk (= 128 bytes per row)
#define NKC (K_DIM / KC)  // 64 chunks
#define NMT (M_DIM / BM)  // 32
#define NNT (N_DIM / BN)  // 43

#define A_BLK_BYTES (BM * 128)       // 16384
#define B_BLK_BYTES (BN * 128)       // 32768
#define STAGE_BYTES (A_BLK_BYTES + B_BLK_BYTES)  // 49152
#define NSTAGES 4
#define SM_TOTAL (2048 + NSTAGES * STAGE_BYTES)  // 198656

#define NCW 16                        // compute warps
#define GTHREADS (NCW * 32 + 32)      // 544 (16 compute + 1 producer)

// Tiled+swizzled scratch in GMEM
__device__ uint4 g_A[(size_t)NMT * NKC * A_BLK_BYTES / 16];   // 33.5 MB
__device__ uint4 g_B[(size_t)NNT * NKC * B_BLK_BYTES / 16];   // 90.2 MB

__host__ __device__ __forceinline__ uint32_t swz128(uint32_t off) {
    return off ^ ((off >> 3) & 0x70u);
}

// ---------------------------------------------------------------------------
// PTX helpers (sm_90-level only; tcgen05 NOT available in this build path)
// ---------------------------------------------------------------------------
__device__ __forceinline__ uint32_t smem_u32(const void* p) {
    uint32_t a;
    asm("{ .reg .u64 t; cvta.to.shared.u64 t, %1; cvt.u32.u64 %0, t; }" : "=r"(a) : "l"(p));
    return a;
}

#define MBAR_INIT(addr, cnt) \
    asm volatile("mbarrier.init.shared.b64 [%0], %1;" :: "r"(addr), "r"(cnt) : "memory")

#define MBAR_EXPECT_TX(addr, bytes) \
    asm volatile("mbarrier.arrive.expect_tx.shared.b64 _, [%0], %1;" :: "r"(addr), "r"(bytes) : "memory")

#define MBAR_ARRIVE(addr) \
    asm volatile("mbarrier.arrive.shared.b64 _, [%0];" :: "r"(addr) : "memory")

#define MBAR_WAIT(addr, parity) do {                                        \
    uint32_t _m = (addr); uint32_t _p = (parity); uint32_t _d;              \
    asm volatile("{\n\t.reg .pred p;\n\t"                                   \
        "mbarrier.try_wait.parity.acquire.cta.shared::cta.b64 p, [%1], %2;\n\t" \
        "selp.b32 %0, 1, 0, p;\n\t}"                                        \
        : "=r"(_d) : "r"(_m), "r"(_p) : "memory");                          \
    if (!_d) {                                                              \
        asm volatile("{\n\t.reg .pred P1;\n\t"                              \
            "W0_%=:\n\t"                                                    \
            "mbarrier.try_wait.parity.acquire.cta.shared::cta.b64 P1, [%0], %1, 0x989680;\n\t" \
            "@P1 bra.uni W1_%=;\n\t"                                        \
            "bra.uni W0_%=;\n\t"                                            \
            "W1_%=:\n\t}" :: "r"(_m), "r"(_p) : "memory");                  \
    }                                                                       \
} while (0)

__device__ __forceinline__ void bulk_ld(uint32_t dst, const void* src, uint32_t bytes,
                                        uint32_t mbar) {
    asm volatile(
        "cp.async.bulk.shared::cluster.global.mbarrier::complete_tx::bytes [%0], [%1], %2, [%3];"
        :: "r"(dst), "l"(src), "r"(bytes), "r"(mbar) : "memory");
}

__device__ __forceinline__ void ldsm4(uint32_t* r, uint32_t addr) {
    asm volatile("ldmatrix.sync.aligned.m8n8.x4.shared.b16 {%0,%1,%2,%3}, [%4];\n"
                 : "=r"(r[0]), "=r"(r[1]), "=r"(r[2]), "=r"(r[3]) : "r"(addr));
}
__device__ __forceinline__ void mma16816(float* c, const uint32_t* a, uint32_t b0, uint32_t b1) {
    asm volatile(
        "mma.sync.aligned.m16n8k16.row.col.f32.f16.f16.f32 "
        "{%0,%1,%2,%3}, {%4,%5,%6,%7}, {%8,%9}, {%0,%1,%2,%3};\n"
        : "+f"(c[0]), "+f"(c[1]), "+f"(c[2]), "+f"(c[3])
        : "r"(a[0]), "r"(a[1]), "r"(a[2]), "r"(a[3]), "r"(b0), "r"(b1));
}

// ---------------------------------------------------------------------------
// Kernel 1: x' = H (s2 * H (s1 * x)) / 128, warp-shuffle FWHT, tiled swizzled
// ---------------------------------------------------------------------------
__global__ __launch_bounds__(256) void transform_x_kernel(
    const float* __restrict__ x, const float* __restrict__ s1,
    const float* __restrict__ s2, unsigned char* __restrict__ At) {
    const int lane = threadIdx.x & 31;
    const int wrp = threadIdx.x >> 5;
    const int pair = blockIdx.x * 8 + wrp;
    const int row = pair >> 5;
    const int grp = pair & 31;

    const float4 xv = *(const float4*)(x + (size_t)row * K_DIM + grp * GROUP + lane * 4);
    const float4 s1v = *(const float4*)(s1 + lane * 4);
    const float4 s2v = *(const float4*)(s2 + lane * 4);

    float v[4] = { xv.x * s1v.x, xv.y * s1v.y, xv.z * s1v.z, xv.w * s1v.w };

#pragma unroll
    for (int pass = 0; pass < 2; pass++) {
        float t0 = v[0] + v[1], t1 = v[0] - v[1];
        float t2 = v[2] + v[3], t3 = v[2] - v[3];
        v[0] = t0 + t2; v[2] = t0 - t2;
        v[1] = t1 + t3; v[3] = t1 - t3;
#pragma unroll
        for (int xm = 1; xm <= 16; xm <<= 1) {
            bool hi = (lane & xm) != 0;
#pragma unroll
            for (int j = 0; j < 4; j++) {
                float o = __shfl_xor_sync(0xFFFFFFFFu, v[j], xm);
                v[j] = hi ? (o - v[j]) : (v[j] + o);
            }
        }
        if (pass == 0) {
            v[0] *= s2v.x; v[1] *= s2v.y; v[2] *= s2v.z; v[3] *= s2v.w;
        }
    }

    const float sc = 1.0f / 128.0f;
    __half2 h01 = __floats2half2_rn(v[0] * sc, v[1] * sc);
    __half2 h23 = __floats2half2_rn(v[2] * sc, v[3] * sc);

    const int mt = row >> 7, r = row & 127;
    const int e = 4 * lane;
    const int kc = grp * 2 + (e >> 6);
    const int c = e & 63;
    const size_t base = ((size_t)mt * NKC + kc) * A_BLK_BYTES;
    const uint32_t off = swz128((uint32_t)(r * 128 + c * 2));
    uint2 val = { *(uint32_t*)&h01, *(uint32_t*)&h23 };
    *(uint2*)(At + base + off) = val;
}

// ---------------------------------------------------------------------------
// Kernel 2: dequant W -> tiled swizzled layout
// ---------------------------------------------------------------------------
__global__ __launch_bounds__(256) void dequant_kernel(
    const int* __restrict__ pw, const float* __restrict__ norms,
    const float* __restrict__ cent, unsigned char* __restrict__ Bt) {
    __shared__ float c[16];
    if (threadIdx.x < 16) c[threadIdx.x] = cent[threadIdx.x];
    __syncthreads();

    const int idx = blockIdx.x * 256 + threadIdx.x;
    const int o = idx >> 11;
    const int p = idx & 2047;
    const unsigned b = ((unsigned)pw[idx]) & 0xFFu;
    const float norm = __ldg(&norms[o * 32 + (p >> 6)]);
    __half2 h2 = __floats2half2_rn(c[b & 15u] * norm, c[b >> 4] * norm);

    const int nt = o >> 8, r = o & 255;
    const int kc = p >> 5;
    const uint32_t off = swz128((uint32_t)(r * 128 + (p & 31) * 4));
    const size_t base = ((size_t)nt * NKC + kc) * B_BLK_BYTES;
    *(uint32_t*)(Bt + base + off) = *(uint32_t*)&h2;
}

// ---------------------------------------------------------------------------
// Kernel 3: mma.sync GEMM, 128x256 CTA tile, 16 compute warps (64x32 each)
// + 1 producer warp; 4-stage cp.async.bulk pipeline.
// 4 compute warps per SMSP hide LDSM latency (round-4: 2/SMSP -> tensor 68.7%).
// ---------------------------------------------------------------------------
extern __shared__ unsigned char dsm[];

__global__ __launch_bounds__(GTHREADS, 1) void gemm_kernel(
    const unsigned char* __restrict__ At, const unsigned char* __restrict__ Bt,
    const float* __restrict__ bias, float* __restrict__ C) {
    const int tid = threadIdx.x;
    const int wid = tid >> 5;
    const int lane = tid & 31;
    const uint32_t sb = (smem_u32(dsm) + 1023) & ~1023u;

    const int mt = blockIdx.x;
    const int nt = blockIdx.y;
    const unsigned char* Ag = At + (size_t)mt * NKC * A_BLK_BYTES;
    const unsigned char* Bg = Bt + (size_t)nt * NKC * B_BLK_BYTES;

    if (tid == 0) {
#pragma unroll
        for (int s = 0; s < NSTAGES; s++) {
            MBAR_INIT(sb + 8 * s, 1);         // full[s]
            MBAR_INIT(sb + 32 + 8 * s, NCW);  // empty[s]
        }
        asm volatile("fence.proxy.async.shared::cta;" ::: "memory");
    }
    __syncthreads();

    if (wid == NCW) {
        // ---------------- producer warp (lane 0 only) ----------------
        if (lane == 0) {
            for (int j = 0; j < NKC; j++) {
                const int s = j & 3;
                if (j >= NSTAGES) {
                    MBAR_WAIT(sb + 32 + 8 * s, ((j >> 2) - 1) & 1);
                }
                const uint32_t full = sb + 8 * s;
                MBAR_EXPECT_TX(full, STAGE_BYTES);
                const uint32_t st = sb + 1024 + s * STAGE_BYTES;
                bulk_ld(st, Ag + (size_t)j * A_BLK_BYTES, A_BLK_BYTES, full);
                bulk_ld(st + A_BLK_BYTES, Bg + (size_t)j * B_BLK_BYTES, B_BLK_BYTES, full);
            }
        }
        return;
    }

    // ---------------- compute warps 0..15: warp tile 64x32 ----------------
    const int wm = (wid >> 3) * 64;   // 0 or 64
    const int wn = (wid & 7) * 32;    // 0..224

    float acc[4][4][4];
#pragma unroll
    for (int i = 0; i < 4; i++)
#pragma unroll
        for (int j = 0; j < 4; j++)
#pragma unroll
            for (int k = 0; k < 4; k++) acc[i][j][k] = 0.0f;

    // ldmatrix lane addressing
    const int a_row = lane & 15;
    const int a_colh = (lane >> 4) * 8;
    const int b_row = (lane & 7) + (lane >> 4) * 8;
    const int b_colh = ((lane >> 3) & 1) * 8;

    for (int j = 0; j < NKC; j++) {
        const int s = j & 3;
        MBAR_WAIT(sb + 8 * s, (j >> 2) & 1);
        const uint32_t as = sb + 1024 + s * STAGE_BYTES;
        const uint32_t bs = as + A_BLK_BYTES;

#pragma unroll
        for (int ks = 0; ks < 4; ks++) {
            uint32_t afr[4][4];
#pragma unroll
            for (int m = 0; m < 4; m++)
                ldsm4(afr[m], as + swz128((uint32_t)((wm + m * 16 + a_row) * 128 +
                                                     (ks * 16 + a_colh) * 2)));
            uint32_t bfr[2][4];
#pragma unroll
            for (int nb = 0; nb < 2; nb++)
                ldsm4(bfr[nb], bs + swz128((uint32_t)((wn + nb * 16 + b_row) * 128 +
                                                      (ks * 16 + b_colh) * 2)));
#pragma unroll
            for (int m = 0; m < 4; m++) {
#pragma unroll
                for (int n = 0; n < 4; n++) {
                    mma16816(acc[m][n], afr[m], bfr[n >> 1][(n & 1) * 2],
                             bfr[n >> 1][(n & 1) * 2 + 1]);
                }
            }
        }
        if (lane == 0) MBAR_ARRIVE(sb + 32 + 8 * s);
    }

    // ---------------- epilogue ----------------
    const int gid = lane >> 2;
    const int tq = lane & 3;
    const int bm = mt * BM, bn = nt * BN;
#pragma unroll
    for (int m = 0; m < 4; m++) {
        const int row0 = bm + wm + m * 16 + gid;
#pragma unroll
        for (int n = 0; n < 4; n++) {
            const int col0 = bn + wn + n * 8 + tq * 2;
            const float bz0 = __ldg(&bias[col0]);
            const float bz1 = __ldg(&bias[col0 + 1]);
            float2 v0 = { acc[m][n][0] + bz0, acc[m][n][1] + bz1 };
            float2 v1 = { acc[m][n][2] + bz0, acc[m][n][3] + bz1 };
            *(float2*)(C + (size_t)row0 * N_DIM + col0) = v0;
            *(float2*)(C + (size_t)(row0 + 8) * N_DIM + col0) = v1;
        }
    }
}

// ---------------------------------------------------------------------------
// Launch
// ---------------------------------------------------------------------------
extern "C" void kernel_launch(void* const* d_in, const int* in_sizes, int n_in,
                              void* d_out, int out_size) {
    const float* x     = (const float*)d_in[0];
    const int*   pw    = (const int*)d_in[1];
    const float* norms = (const float*)d_in[2];
    const float* cent  = (const float*)d_in[3];
    const float* s1    = (const float*)d_in[4];
    const float* s2    = (const float*)d_in[5];
    const float* bias  = (const float*)d_in[6];
    float* out = (float*)d_out;

    unsigned char *At, *Bt;
    cudaGetSymbolAddress((void**)&At, g_A);
    cudaGetSymbolAddress((void**)&Bt, g_B);

    transform_x_kernel<<<(M_DIM * 32) / 8, 256>>>(x, s1, s2, At);
    dequant_kernel<<<(N_DIM * (K_DIM / 2)) / 256, 256>>>(pw, norms, cent, Bt);

    static bool attr_set = false;
    if (!attr_set) {
        cudaFuncSetAttribute(gemm_kernel, cudaFuncAttributeMaxDynamicSharedMemorySize,
                             SM_TOTAL);
        attr_set = true;
    }
    dim3 grid(NMT, NNT);
    gemm_kernel<<<grid, GTHREADS, SM_TOTAL>>>(At, Bt, bias, out);
}